// round 7
// baseline (speedup 1.0000x reference)
#include <cuda_runtime.h>
#include <cuda_fp16.h>
#include <cstdint>

// ---------------------------------------------------------------------------
// out[n,o] = sum_s attn[s] * (X[s] @ W[s])[n,o] + bias[o]
// R7: stage = support s; A 64KB + B 32KB via single cp.async.bulk each,
//     2-slot ring. Per-WARP private ping-pong staging for fp32->fp16 convert:
//     no block syncs inside a support (only 1 per support for slot reuse).
// ---------------------------------------------------------------------------

#define NROWS    200000
#define BLOCK_M  128
#define NSUP     8

#define A_FP32_BYTES 65536                   // 128 rows x 128 f32
#define B_BYTES      32768                   // 128 o x 128 i f16 (pre-swizzled)
#define SLOT_BYTES   (A_FP32_BYTES + B_BYTES)    // 98304

#define SMEM_MBAR    0                       // 2 x 8B
#define SMEM_STG     1024                    // 8 warps x 2 x 2048
#define SMEM_SLOT0   (1024 + 32768)          // 33792
#define SMEM_TOTAL   (SMEM_SLOT0 + 2 * SLOT_BYTES)   // 230400 (<= 232448)

// B: stage-major fp16, attn-folded, swizzled: (s,o,i) ->
//   s*16384 + o*128 + ((i>>3) ^ (o&7))*8 + (i&7)
__device__ __half g_Wh[NSUP * 128 * 128];

// ---- helpers ---------------------------------------------------------------

__device__ __forceinline__ uint32_t smem_u32(const void* p) {
    uint32_t a;
    asm("{ .reg .u64 t; cvta.to.shared.u64 t, %1; cvt.u32.u64 %0, t; }"
        : "=r"(a) : "l"(p));
    return a;
}

__device__ __forceinline__ void ldsm_x4(uint32_t* r, uint32_t addr) {
    asm volatile("ldmatrix.sync.aligned.m8n8.x4.shared.b16 {%0,%1,%2,%3}, [%4];"
                 : "=r"(r[0]), "=r"(r[1]), "=r"(r[2]), "=r"(r[3]) : "r"(addr));
}

__device__ __forceinline__ void mma_f16(float* c, const uint32_t* a,
                                        uint32_t b0, uint32_t b1) {
    asm volatile(
        "mma.sync.aligned.m16n8k16.row.col.f32.f16.f16.f32 "
        "{%0,%1,%2,%3}, {%4,%5,%6,%7}, {%8,%9}, {%0,%1,%2,%3};"
        : "+f"(c[0]), "+f"(c[1]), "+f"(c[2]), "+f"(c[3])
        : "r"(a[0]), "r"(a[1]), "r"(a[2]), "r"(a[3]), "r"(b0), "r"(b1));
}

__device__ __forceinline__ void mbar_wait(uint32_t mbar, uint32_t parity) {
    asm volatile(
        "{\n\t"
        ".reg .pred P1;\n\t"
        "WAIT_LOOP_%=:\n\t"
        "mbarrier.try_wait.parity.acquire.cta.shared::cta.b64 P1, [%0], %1, 0x989680;\n\t"
        "@P1 bra.uni WAIT_DONE_%=;\n\t"
        "bra.uni WAIT_LOOP_%=;\n\t"
        "WAIT_DONE_%=:\n\t"
        "}"
        :: "r"(mbar), "r"(parity) : "memory");
}

// single-thread: issue the 2 bulk copies for support s into slot
__device__ __forceinline__ void issue_stage(const float* __restrict__ X,
                                            uint32_t sb, int slot, int s,
                                            int m0, uint32_t a_bytes) {
    const uint32_t mbar = sb + SMEM_MBAR + slot * 8;
    const uint32_t aDst = sb + SMEM_SLOT0 + slot * SLOT_BYTES;
    asm volatile("mbarrier.arrive.expect_tx.shared.b64 _, [%0], %1;"
                 :: "r"(mbar), "r"(a_bytes + (uint32_t)B_BYTES) : "memory");
    const float* gA = X + ((size_t)s * NROWS + m0) * 128;
    asm volatile(
        "cp.async.bulk.shared::cta.global.mbarrier::complete_tx::bytes "
        "[%0], [%1], %2, [%3];"
        :: "r"(aDst), "l"(gA), "r"(a_bytes), "r"(mbar) : "memory");
    const void* gB = (const void*)(g_Wh + (size_t)s * 16384);
    asm volatile(
        "cp.async.bulk.shared::cta.global.mbarrier::complete_tx::bytes "
        "[%0], [%1], %2, [%3];"
        :: "r"(aDst + (uint32_t)A_FP32_BYTES), "l"(gB), "r"((uint32_t)B_BYTES),
           "r"(mbar) : "memory");
}

// ---- prep: stage-major, ldmatrix-swizzled fp16 B ----------------------------

__global__ void prep_kernel(const float* __restrict__ W, const float* __restrict__ attn) {
    int idx = blockIdx.x * 256 + threadIdx.x;
    if (idx >= NSUP * 128 * 128) return;
    int s = idx >> 14;
    int o = (idx >> 7) & 127;
    int i = idx & 127;
    float v = attn[s] * W[((s << 7) + i) * 128 + o];
    int dst = s * 16384 + o * 128 + ((((i >> 3) ^ (o & 7))) << 3) + (i & 7);
    g_Wh[dst] = __float2half_rn(v);
}

// ---- main GEMM --------------------------------------------------------------

__global__ void __launch_bounds__(256, 1)
mgc_kernel(const float* __restrict__ X, const float* __restrict__ bias,
           float* __restrict__ out) {
    extern __shared__ char smem[];
    const uint32_t sb  = smem_u32(smem);
    const int tid = threadIdx.x;
    const int lid = tid & 31;
    const int wid = tid >> 5;
    const int wm  = wid >> 1;          // 0..3  (32-row slices)
    const int wn  = wid & 1;           // 0..1  (64-col slices)
    const int m0  = blockIdx.x * BLOCK_M;

    const uint32_t a_bytes =
        (uint32_t)((NROWS - m0 >= BLOCK_M ? BLOCK_M : NROWS - m0) * 512);

    if (tid == 0) {
        asm volatile("mbarrier.init.shared.b64 [%0], 1;" :: "r"(sb + SMEM_MBAR) : "memory");
        asm volatile("mbarrier.init.shared.b64 [%0], 1;" :: "r"(sb + SMEM_MBAR + 8) : "memory");
        asm volatile("fence.proxy.async.shared::cta;" ::: "memory");
    }
    __syncthreads();
    if (tid == 0) {
        issue_stage(X, sb, 0, 0, m0, a_bytes);
        issue_stage(X, sb, 1, 1, m0, a_bytes);
    }

    // geometry
    const uint32_t stgW = sb + SMEM_STG + (uint32_t)wid * 4096;  // + pp*2048
    const int rA_loc  = lid & 15;                   // + mt*16: staging row
    const int a_usel  = (lid >> 4) & 1;
    const int o_base  = wn * 64 + (lid & 7) + ((lid >> 4) & 1) * 8;  // + 16*p
    const int b_usel  = (lid >> 3) & 1;

    float acc[2][8][4];
    #pragma unroll
    for (int mt = 0; mt < 2; mt++)
        #pragma unroll
        for (int nt = 0; nt < 8; nt++)
            #pragma unroll
            for (int v = 0; v < 4; v++) acc[mt][nt][v] = 0.f;

    for (int s = 0; s < NSUP; s++) {
        const int slot = s & 1;
        mbar_wait(sb + SMEM_MBAR + slot * 8, (s >> 1) & 1);

        const uint32_t aSlot = sb + SMEM_SLOT0 + slot * SLOT_BYTES;
        const uint32_t bSlot = aSlot + A_FP32_BYTES;
        // this lane converts row (wm*32 + lid) of the A tile
        const uint32_t aRowBase = aSlot + (uint32_t)((wm * 32 + lid) * 512);
        const uint32_t stRowBase = (uint32_t)(lid * 64);
        const int rsw = (lid >> 1) & 3;             // store-side XOR term

        #pragma unroll
        for (int c = 0; c < 4; c++) {               // k32 chunks
            const uint32_t stg = stgW + (uint32_t)((c & 1) * 2048);

            // ---- warp-local convert: 32 rows x 32 f32 -> fp16 staging ----
            #pragma unroll
            for (int j = 0; j < 8; j++) {
                int fc = (j + lid) & 7;             // staggered 16B chunk
                float x, y, z, w;
                asm("ld.shared.v4.f32 {%0,%1,%2,%3}, [%4];"
                    : "=f"(x), "=f"(y), "=f"(z), "=f"(w)
                    : "r"(aRowBase + (uint32_t)(c * 128 + fc * 16)));
                uint32_t h0, h1;
                asm("cvt.rn.f16x2.f32 %0, %1, %2;" : "=r"(h0) : "f"(y), "f"(x));
                asm("cvt.rn.f16x2.f32 %0, %1, %2;" : "=r"(h1) : "f"(w), "f"(z));
                asm volatile("st.shared.v2.b32 [%0], {%1,%2};"
                    :: "r"(stg + stRowBase +
                           (uint32_t)((((fc >> 1) ^ rsw) << 4) + (fc & 1) * 8)),
                       "r"(h0), "r"(h1) : "memory");
            }
            __syncwarp();

            // ---- 2 x k16 MMA steps (warp-local) --------------------------
            #pragma unroll
            for (int jl = 0; jl < 2; jl++) {
                uint32_t af[2][4];
                #pragma unroll
                for (int mt = 0; mt < 2; mt++) {
                    int r = mt * 16 + rA_loc;
                    int u = 2 * jl + a_usel;
                    uint32_t addr = stg + (uint32_t)(r * 64 +
                                       ((u ^ ((r >> 1) & 3)) << 4));
                    ldsm_x4(af[mt], addr);
                }
                uint32_t bq[4][4];
                #pragma unroll
                for (int p = 0; p < 4; p++) {
                    int o = o_base + 16 * p;
                    int u = 4 * c + 2 * jl + b_usel;
                    uint32_t addr = bSlot + (uint32_t)(o * 256 +
                                        ((u ^ (o & 7)) << 4));
                    ldsm_x4(bq[p], addr);
                }
                #pragma unroll
                for (int mt = 0; mt < 2; mt++)
                    #pragma unroll
                    for (int p = 0; p < 4; p++) {
                        mma_f16(acc[mt][2 * p],     af[mt], bq[p][0], bq[p][1]);
                        mma_f16(acc[mt][2 * p + 1], af[mt], bq[p][2], bq[p][3]);
                    }
            }
        }

        __syncthreads();                 // slot fully consumed by all warps
        if (tid == 0 && s + 2 < NSUP)
            issue_stage(X, sb, slot, s + 2, m0, a_bytes);
    }

    // ---- epilogue: acc + bias -> out ----------------------------------------
    const int tig = lid & 3;
    const int g   = lid >> 2;

    float2 bv[8];
    #pragma unroll
    for (int nt = 0; nt < 8; nt++) {
        int cidx = wn * 64 + nt * 8 + 2 * tig;
        bv[nt].x = __ldg(&bias[cidx]);
        bv[nt].y = __ldg(&bias[cidx + 1]);
    }

    #pragma unroll
    for (int mt = 0; mt < 2; mt++) {
        int mrow = m0 + wm * 32 + mt * 16 + g;
        #pragma unroll
        for (int half = 0; half < 2; half++) {
            int m = mrow + half * 8;
            if (m < NROWS) {
                float* po = out + (size_t)m * 128 + wn * 64;
                #pragma unroll
                for (int nt = 0; nt < 8; nt++) {
                    float2 v;
                    v.x = acc[mt][nt][2 * half + 0] + bv[nt].x;
                    v.y = acc[mt][nt][2 * half + 1] + bv[nt].y;
                    *reinterpret_cast<float2*>(po + nt * 8 + 2 * tig) = v;
                }
            }
        }
    }
}

// ---- launch -----------------------------------------------------------------

extern "C" void kernel_launch(void* const* d_in, const int* in_sizes, int n_in,
                              void* d_out, int out_size) {
    const float* X    = (const float*)d_in[0];   // (8, 200000, 128) f32
    const float* W    = (const float*)d_in[1];   // (8, 128, 128)    f32
    const float* attn = (const float*)d_in[2];   // (8,)             f32
    const float* bias = (const float*)d_in[3];   // (128,)           f32
    float* out = (float*)d_out;                  // (200000, 128)    f32

    cudaFuncSetAttribute(mgc_kernel, cudaFuncAttributeMaxDynamicSharedMemorySize,
                         SMEM_TOTAL);

    prep_kernel<<<(NSUP * 128 * 128 + 255) / 256, 256>>>(W, attn);

    int grid = (NROWS + BLOCK_M - 1) / BLOCK_M;   // 1563
    mgc_kernel<<<grid, 256, SMEM_TOTAL>>>(X, bias, out);
}

// round 8
// speedup vs baseline: 2.8135x; 2.8135x over previous
#include <cuda_runtime.h>
#include <cuda_fp16.h>
#include <cstdint>

// ---------------------------------------------------------------------------
// out[n,o] = sum_s attn[s] * (X[s] @ W[s])[n,o] + bias[o]
// R8: R6 skeleton (stage = support, single big bulks) with:
//     - separate A/B mbarrier rings (A freed by convert -> early re-issue)
//     - one full-tile fp32->fp16 convert into 32KB staging (2 syncs/support)
// ---------------------------------------------------------------------------

#define NROWS    200000
#define BLOCK_M  128
#define NSUP     8

#define A_FP32_BYTES 65536                   // 128 rows x 128 f32
#define B_BYTES      32768                   // 128 o x 128 i f16 (pre-swizzled)

#define SMEM_MBAR    0                       // A0,A1,B0,B1 (4 x 8B)
#define SMEM_STG     1024                    // 32KB staging (4 x 8KB chunks)
#define SMEM_A0      (1024 + 32768)          // 33792: A ring 2 x 64KB
#define SMEM_B0      (SMEM_A0 + 2 * A_FP32_BYTES)   // 164864: B ring 2 x 32KB
#define SMEM_TOTAL   (SMEM_B0 + 2 * B_BYTES)        // 230400

// B: stage-major fp16, attn-folded, swizzled: (s,o,i) ->
//   s*16384 + o*128 + ((i>>3) ^ (o&7))*8 + (i&7)
__device__ __half g_Wh[NSUP * 128 * 128];

// ---- helpers ---------------------------------------------------------------

__device__ __forceinline__ uint32_t smem_u32(const void* p) {
    uint32_t a;
    asm("{ .reg .u64 t; cvta.to.shared.u64 t, %1; cvt.u32.u64 %0, t; }"
        : "=r"(a) : "l"(p));
    return a;
}

__device__ __forceinline__ void ldsm_x4(uint32_t* r, uint32_t addr) {
    asm volatile("ldmatrix.sync.aligned.m8n8.x4.shared.b16 {%0,%1,%2,%3}, [%4];"
                 : "=r"(r[0]), "=r"(r[1]), "=r"(r[2]), "=r"(r[3]) : "r"(addr));
}

__device__ __forceinline__ void mma_f16(float* c, const uint32_t* a,
                                        uint32_t b0, uint32_t b1) {
    asm volatile(
        "mma.sync.aligned.m16n8k16.row.col.f32.f16.f16.f32 "
        "{%0,%1,%2,%3}, {%4,%5,%6,%7}, {%8,%9}, {%0,%1,%2,%3};"
        : "+f"(c[0]), "+f"(c[1]), "+f"(c[2]), "+f"(c[3])
        : "r"(a[0]), "r"(a[1]), "r"(a[2]), "r"(a[3]), "r"(b0), "r"(b1));
}

__device__ __forceinline__ void mbar_wait(uint32_t mbar, uint32_t parity) {
    asm volatile(
        "{\n\t"
        ".reg .pred P1;\n\t"
        "WAIT_LOOP_%=:\n\t"
        "mbarrier.try_wait.parity.acquire.cta.shared::cta.b64 P1, [%0], %1, 0x989680;\n\t"
        "@P1 bra.uni WAIT_DONE_%=;\n\t"
        "bra.uni WAIT_LOOP_%=;\n\t"
        "WAIT_DONE_%=:\n\t"
        "}"
        :: "r"(mbar), "r"(parity) : "memory");
}

__device__ __forceinline__ void issue_A(const float* __restrict__ X,
                                        uint32_t sb, int slot, int s,
                                        int m0, uint32_t a_bytes) {
    const uint32_t mbar = sb + SMEM_MBAR + slot * 8;
    asm volatile("mbarrier.arrive.expect_tx.shared.b64 _, [%0], %1;"
                 :: "r"(mbar), "r"(a_bytes) : "memory");
    const float* gA = X + ((size_t)s * NROWS + m0) * 128;
    asm volatile(
        "cp.async.bulk.shared::cta.global.mbarrier::complete_tx::bytes "
        "[%0], [%1], %2, [%3];"
        :: "r"(sb + SMEM_A0 + slot * A_FP32_BYTES), "l"(gA), "r"(a_bytes),
           "r"(mbar) : "memory");
}

__device__ __forceinline__ void issue_B(uint32_t sb, int slot, int s) {
    const uint32_t mbar = sb + SMEM_MBAR + 16 + slot * 8;
    asm volatile("mbarrier.arrive.expect_tx.shared.b64 _, [%0], %1;"
                 :: "r"(mbar), "r"((uint32_t)B_BYTES) : "memory");
    const void* gB = (const void*)(g_Wh + (size_t)s * 16384);
    asm volatile(
        "cp.async.bulk.shared::cta.global.mbarrier::complete_tx::bytes "
        "[%0], [%1], %2, [%3];"
        :: "r"(sb + SMEM_B0 + slot * B_BYTES), "l"(gB), "r"((uint32_t)B_BYTES),
           "r"(mbar) : "memory");
}

// ---- prep: stage-major, ldmatrix-swizzled fp16 B ----------------------------

__global__ void prep_kernel(const float* __restrict__ W, const float* __restrict__ attn) {
    int idx = blockIdx.x * 256 + threadIdx.x;
    if (idx >= NSUP * 128 * 128) return;
    int s = idx >> 14;
    int o = (idx >> 7) & 127;
    int i = idx & 127;
    float v = attn[s] * W[((s << 7) + i) * 128 + o];
    int dst = s * 16384 + o * 128 + ((((i >> 3) ^ (o & 7))) << 3) + (i & 7);
    g_Wh[dst] = __float2half_rn(v);
}

// ---- main GEMM --------------------------------------------------------------

__global__ void __launch_bounds__(256, 1)
mgc_kernel(const float* __restrict__ X, const float* __restrict__ bias,
           float* __restrict__ out) {
    extern __shared__ char smem[];
    const uint32_t sb  = smem_u32(smem);
    const int tid = threadIdx.x;
    const int lid = tid & 31;
    const int wid = tid >> 5;
    const int wm  = wid >> 1;          // 0..3  (32-row slices)
    const int wn  = wid & 1;           // 0..1  (64-col slices)
    const int m0  = blockIdx.x * BLOCK_M;

    const uint32_t a_bytes =
        (uint32_t)((NROWS - m0 >= BLOCK_M ? BLOCK_M : NROWS - m0) * 512);

    if (tid == 0) {
        #pragma unroll
        for (int j = 0; j < 4; j++)
            asm volatile("mbarrier.init.shared.b64 [%0], 1;"
                         :: "r"(sb + SMEM_MBAR + j * 8) : "memory");
        asm volatile("fence.proxy.async.shared::cta;" ::: "memory");
    }
    __syncthreads();
    if (tid == 0) {
        issue_A(X, sb, 0, 0, m0, a_bytes);
        issue_A(X, sb, 1, 1, m0, a_bytes);
        issue_B(sb, 0, 0);
        issue_B(sb, 1, 1);
    }

    // ldmatrix lane geometry
    const int rA_base = wm * 32 + (lid & 15);       // + mt*16 (staging row)
    const int a_usel  = (lid >> 4) & 1;
    const int o_base  = wn * 64 + (lid & 7) + ((lid >> 4) & 1) * 8;  // + 16*p
    const int b_usel  = (lid >> 3) & 1;

    float acc[2][8][4];
    #pragma unroll
    for (int mt = 0; mt < 2; mt++)
        #pragma unroll
        for (int nt = 0; nt < 8; nt++)
            #pragma unroll
            for (int v = 0; v < 4; v++) acc[mt][nt][v] = 0.f;

    for (int s = 0; s < NSUP; s++) {
        const int slot = s & 1;
        const uint32_t par = (s >> 1) & 1;
        const uint32_t aSlot = sb + SMEM_A0 + slot * A_FP32_BYTES;
        const uint32_t bSlot = sb + SMEM_B0 + slot * B_BYTES;
        const uint32_t stg   = sb + SMEM_STG;

        // ---- A fp32 arrived? then convert full tile into staging ------------
        mbar_wait(sb + SMEM_MBAR + slot * 8, par);

        #pragma unroll
        for (int i = 0; i < 16; i++) {
            int idx = tid + 256 * i;                // 0..4095
            int c   = idx >> 10;
            int q   = idx & 1023;
            int row = q >> 3, fc = q & 7;
            float x, y, z, w;
            asm("ld.shared.v4.f32 {%0,%1,%2,%3}, [%4];"
                : "=f"(x), "=f"(y), "=f"(z), "=f"(w)
                : "r"(aSlot + (uint32_t)(row * 512 + c * 128 + fc * 16)));
            uint32_t h0, h1;
            asm("cvt.rn.f16x2.f32 %0, %1, %2;" : "=r"(h0) : "f"(y), "f"(x));
            asm("cvt.rn.f16x2.f32 %0, %1, %2;" : "=r"(h1) : "f"(w), "f"(z));
            int phys = (fc >> 1) ^ ((row >> 1) & 3);
            asm volatile("st.shared.v2.b32 [%0], {%1,%2};"
                :: "r"(stg + (uint32_t)(c * 8192 + row * 64 + phys * 16 + (fc & 1) * 8)),
                   "r"(h0), "r"(h1) : "memory");
        }
        __syncthreads();                     // staging ready; fp32 slot free
        if (tid == 0 && s + 2 < NSUP)
            issue_A(X, sb, slot, s + 2, m0, a_bytes);   // wide DMA window

        // ---- B arrived? then MMA the whole support --------------------------
        mbar_wait(sb + SMEM_MBAR + 16 + slot * 8, par);

        #pragma unroll
        for (int c = 0; c < 4; c++) {
            #pragma unroll
            for (int jl = 0; jl < 2; jl++) {
                uint32_t af[2][4];
                #pragma unroll
                for (int mt = 0; mt < 2; mt++) {
                    int r = rA_base + mt * 16;
                    int u = 2 * jl + a_usel;
                    uint32_t addr = stg + (uint32_t)(c * 8192 + r * 64 +
                                       ((u ^ ((r >> 1) & 3)) << 4));
                    ldsm_x4(af[mt], addr);
                }
                uint32_t bq[4][4];
                #pragma unroll
                for (int p = 0; p < 4; p++) {
                    int o = o_base + 16 * p;
                    int u = 4 * c + 2 * jl + b_usel;
                    uint32_t addr = bSlot + (uint32_t)(o * 256 +
                                        ((u ^ (o & 7)) << 4));
                    ldsm_x4(bq[p], addr);
                }
                #pragma unroll
                for (int mt = 0; mt < 2; mt++)
                    #pragma unroll
                    for (int p = 0; p < 4; p++) {
                        mma_f16(acc[mt][2 * p],     af[mt], bq[p][0], bq[p][1]);
                        mma_f16(acc[mt][2 * p + 1], af[mt], bq[p][2], bq[p][3]);
                    }
            }
        }

        __syncthreads();                     // staging + B slot consumed
        if (tid == 0 && s + 2 < NSUP)
            issue_B(sb, slot, s + 2);
    }

    // ---- epilogue: acc + bias -> out ----------------------------------------
    const int tig = lid & 3;
    const int g   = lid >> 2;

    float2 bv[8];
    #pragma unroll
    for (int nt = 0; nt < 8; nt++) {
        int cidx = wn * 64 + nt * 8 + 2 * tig;
        bv[nt].x = __ldg(&bias[cidx]);
        bv[nt].y = __ldg(&bias[cidx + 1]);
    }

    #pragma unroll
    for (int mt = 0; mt < 2; mt++) {
        int mrow = m0 + wm * 32 + mt * 16 + g;
        #pragma unroll
        for (int half = 0; half < 2; half++) {
            int m = mrow + half * 8;
            if (m < NROWS) {
                float* po = out + (size_t)m * 128 + wn * 64;
                #pragma unroll
                for (int nt = 0; nt < 8; nt++) {
                    float2 v;
                    v.x = acc[mt][nt][2 * half + 0] + bv[nt].x;
                    v.y = acc[mt][nt][2 * half + 1] + bv[nt].y;
                    *reinterpret_cast<float2*>(po + nt * 8 + 2 * tig) = v;
                }
            }
        }
    }
}

// ---- launch -----------------------------------------------------------------

extern "C" void kernel_launch(void* const* d_in, const int* in_sizes, int n_in,
                              void* d_out, int out_size) {
    const float* X    = (const float*)d_in[0];   // (8, 200000, 128) f32
    const float* W    = (const float*)d_in[1];   // (8, 128, 128)    f32
    const float* attn = (const float*)d_in[2];   // (8,)             f32
    const float* bias = (const float*)d_in[3];   // (128,)           f32
    float* out = (float*)d_out;                  // (200000, 128)    f32

    cudaFuncSetAttribute(mgc_kernel, cudaFuncAttributeMaxDynamicSharedMemorySize,
                         SMEM_TOTAL);

    prep_kernel<<<(NSUP * 128 * 128 + 255) / 256, 256>>>(W, attn);

    int grid = (NROWS + BLOCK_M - 1) / BLOCK_M;   // 1563
    mgc_kernel<<<grid, 256, SMEM_TOTAL>>>(X, bias, out);
}